// round 7
// baseline (speedup 1.0000x reference)
#include <cuda_runtime.h>
#include <cstdint>

#define B_ 256
#define T_ 1024
#define D_ 64
#define H_ 100
#define G_ 400   // 4*H
#define NBLK 128
#define L2E 1.44269504088896f

// Precomputed input-gate contributions, PERMUTED row order:
// xg[b][t][p] holds gate-row ((p&3)*H + (p>>2)).  ~419 MB.
__device__ float g_xg[(size_t)B_ * T_ * G_];

// ---------------------------------------------------------------------------
// Packed f32x2 helpers
// ---------------------------------------------------------------------------
__device__ __forceinline__ unsigned long long ffma2(unsigned long long a,
                                                    unsigned long long b,
                                                    unsigned long long c) {
    unsigned long long d;
    asm("fma.rn.f32x2 %0, %1, %2, %3;" : "=l"(d) : "l"(a), "l"(b), "l"(c));
    return d;
}
__device__ __forceinline__ unsigned long long add2(unsigned long long a,
                                                   unsigned long long b) {
    unsigned long long d;
    asm("add.rn.f32x2 %0, %1, %2;" : "=l"(d) : "l"(a), "l"(b));
    return d;
}
__device__ __forceinline__ unsigned long long pack2(float x, float y) {
    return ((unsigned long long)__float_as_uint(y) << 32) |
           (unsigned long long)__float_as_uint(x);
}
__device__ __forceinline__ float lo2(unsigned long long v) {
    return __uint_as_float((unsigned)v);
}
__device__ __forceinline__ float hi2(unsigned long long v) {
    return __uint_as_float((unsigned)(v >> 32));
}
__device__ __forceinline__ float ex2a(float x) {
    float r; asm("ex2.approx.ftz.f32 %0, %1;" : "=f"(r) : "f"(x)); return r;
}
__device__ __forceinline__ float rcpa(float x) {
    float r; asm("rcp.approx.ftz.f32 %0, %1;" : "=f"(r) : "f"(x)); return r;
}
// sigmoid(x) = 1 - 1/(e^x+1)  (lm=log2e, s=1);  tanh(x) = 1 - 2/(e^2x+1)
__device__ __forceinline__ float uact(float x, float lm, float s) {
    return 1.0f - s * rcpa(ex2a(lm * x) + 1.0f);
}

// ---------------------------------------------------------------------------
// Kernel 1: xg[b,t,p] = x[b,t,:] . W_ih[row,:] + (b_ih+b_hh)[row],
//           row = (p&3)*H + (p>>2)  (quad-permuted for the lstm kernel).
// Reg-lean version: W fragment re-loaded per 16-k chunk via __ldg (L1-hot),
// 8 independent accumulator chains over an 8-timestep tile.
// __launch_bounds__(512,2) -> 2 blocks/SM for latency coverage.
// ---------------------------------------------------------------------------
__global__ __launch_bounds__(512, 2)
void xg_kernel(const float* __restrict__ x,
               const float* __restrict__ W_ih,
               const float* __restrict__ b_ih,
               const float* __restrict__ b_hh) {
    __shared__ ulonglong2 xs[64][16];   // 64 t x 64 k fp32 tile (16 KB)

    const int b   = blockIdx.y;
    const int t0  = blockIdx.x * 64;
    const int tid = threadIdx.x;

    {   // coalesced float4 tile load
        const float4* src = (const float4*)(x + ((size_t)b * T_ + t0) * D_);
        float4* dst = (float4*)xs;
        for (int i = tid; i < 64 * 16; i += 512) dst[i] = src[i];
    }

    float bias = 0.0f;
    const float4* wrow = nullptr;
    if (tid < G_) {
        const int row = (tid & 3) * H_ + (tid >> 2);
        wrow = (const float4*)(W_ih + (size_t)row * D_);
        bias = b_ih[row] + b_hh[row];
    }
    __syncthreads();

    if (tid < G_) {
        float* out = g_xg + ((size_t)b * T_ + t0) * G_ + tid;
#pragma unroll
        for (int tb = 0; tb < 8; tb++) {
            unsigned long long acc2[8] = {0, 0, 0, 0, 0, 0, 0, 0};
#pragma unroll
            for (int kc = 0; kc < 4; kc++) {
                // W fragment for k in [kc*16, kc*16+16): 8 f32x2 (L1 hit)
                unsigned long long w2[8];
#pragma unroll
                for (int m = 0; m < 4; m++) {
                    float4 v = __ldg(wrow + kc * 4 + m);
                    w2[2 * m]     = pack2(v.x, v.y);
                    w2[2 * m + 1] = pack2(v.z, v.w);
                }
#pragma unroll
                for (int t = 0; t < 8; t++) {
#pragma unroll
                    for (int m = 0; m < 4; m++) {
                        ulonglong2 xv = xs[tb * 8 + t][kc * 4 + m]; // LDS.128
                        acc2[t] = ffma2(w2[2 * m],     xv.x, acc2[t]);
                        acc2[t] = ffma2(w2[2 * m + 1], xv.y, acc2[t]);
                    }
                }
            }
#pragma unroll
            for (int t = 0; t < 8; t++) {
                out[(size_t)(tb * 8 + t) * G_] =
                    lo2(acc2[t]) + hi2(acc2[t]) + bias;
            }
        }
    }
}

// ---------------------------------------------------------------------------
// Kernel 2: recurrence, split-k, ONE barrier per step. (R5 — best measured.)
// 128 blocks x 2 batch rows, 800 threads. Thread: r = tid>>1 (permuted row,
// gate=r&3, j=r>>2), s = tid&1 (k-half AND final batch owner).
// ---------------------------------------------------------------------------
__global__ __launch_bounds__(800, 1)
void lstm_kernel(const float* __restrict__ h0,
                 const float* __restrict__ c0,
                 const float* __restrict__ W_hh,
                 const float* __restrict__ W_fc,
                 const float* __restrict__ b_fc,
                 float* __restrict__ out) {
    __shared__ float4 hs4[2][50];      // [buf][k-pair i] = {h0_2i,h0_2i+1,h1_2i,h1_2i+1}
    __shared__ float wfc_s[H_];

    const int tid    = threadIdx.x;
    const int batch0 = blockIdx.x * 2;
    const int r      = tid >> 1;       // permuted gate-row
    const int s      = tid & 1;        // k-half + batch owner
    const int gate   = r & 3;
    const int j      = r >> 2;

    // --- init h buffer 0, wfc ---
    if (tid < H_) {
        int i = tid >> 1, comp = tid & 1;
        ((float*)&hs4[0][i])[comp]     = h0[(size_t)(batch0)     * H_ + tid];
        ((float*)&hs4[0][i])[2 + comp] = h0[(size_t)(batch0 + 1) * H_ + tid];
        wfc_s[tid] = W_fc[tid];
    }

    // --- weights: k-pairs [s*25, s*25+25) of W_hh row (gate*H + j) ---
    unsigned long long w2[25];
    {
        const float2* wrow =
            (const float2*)(W_hh + (size_t)(gate * H_ + j) * H_) + s * 25;
#pragma unroll
        for (int i = 0; i < 25; i++) {
            float2 v = wrow[i];
            w2[i] = pack2(v.x, v.y);
        }
    }
    float lm = (gate == 2) ? 2.0f * L2E : L2E;
    float sc = (gate == 2) ? 2.0f : 1.0f;

    // c owned by gate-0 threads: (unit j, batch s)
    float cr = (gate == 0) ? c0[(size_t)(batch0 + s) * H_ + j] : 0.0f;

    // xg stream for my batch (batch0+s), permuted row r
    const float* xp = g_xg + (size_t)(batch0 + s) * T_ * G_ + r;
    float xgc = xp[0];

    __syncthreads();

    int cur = 0;
    for (int t = 0; t < T_; t++) {
        float xgn = (t + 1 < T_) ? xp[(size_t)(t + 1) * G_] : 0.0f;  // prefetch

        // matvec over my k-half, both batches from one load + one weight reg
        const float4* hbase = hs4[cur] + s * 25;
        unsigned long long a0 = 0ull, b0 = 0ull;
#pragma unroll
        for (int i = 0; i < 25; i++) {
            float4 hv = hbase[i];                  // LDS.128
            a0 = ffma2(w2[i], pack2(hv.x, hv.y), a0);
            b0 = ffma2(w2[i], pack2(hv.z, hv.w), b0);
        }
        float p0 = lo2(a0) + hi2(a0);              // batch0 partial (my half)
        float p1 = lo2(b0) + hi2(b0);              // batch1 partial

        // combine k-halves with partner lane (tid^1)
        float q0 = __shfl_xor_sync(0xffffffffu, p0, 1);
        float q1 = __shfl_xor_sync(0xffffffffu, p1, 1);
        float full = (s ? (p1 + q1) : (p0 + q0)) + xgc;

        float gv = uact(full, lm, sc);             // my gate, my batch

        // gather {f,g,o} to the gate-0 lane (even deltas keep batch parity)
        float fv = __shfl_down_sync(0xffffffffu, gv, 2);
        float gg = __shfl_down_sync(0xffffffffu, gv, 4);
        float ov = __shfl_down_sync(0xffffffffu, gv, 6);

        if (gate == 0) {                           // owns c for (j, batch s)
            cr = fv * cr + gv * gg;
            float hv = ov * uact(cr, 2.0f * L2E, 2.0f);
            ((float*)&hs4[cur ^ 1][j >> 1])[(j & 1) + 2 * s] = hv;
        }
        xgc = xgn;
        __syncthreads();
        cur ^= 1;
    }

    // FC head: out[b] = h_T . W_fc + b_fc   (h_T is in hs4[cur])
    if (tid < 2) {
        float acc = b_fc[0];
#pragma unroll 4
        for (int jj = 0; jj < H_; jj++) {
            float hv = ((const float*)&hs4[cur][jj >> 1])[(jj & 1) + 2 * tid];
            acc += hv * wfc_s[jj];
        }
        out[batch0 + tid] = acc;
    }
}

// ---------------------------------------------------------------------------
extern "C" void kernel_launch(void* const* d_in, const int* in_sizes, int n_in,
                              void* d_out, int out_size) {
    const float* x    = (const float*)d_in[0];
    const float* h0   = (const float*)d_in[1];
    const float* c0   = (const float*)d_in[2];
    const float* W_ih = (const float*)d_in[3];
    const float* W_hh = (const float*)d_in[4];
    const float* b_ih = (const float*)d_in[5];
    const float* b_hh = (const float*)d_in[6];
    const float* W_fc = (const float*)d_in[7];
    const float* b_fc = (const float*)d_in[8];
    float* out = (float*)d_out;

    dim3 grid1(T_ / 64, B_);
    xg_kernel<<<grid1, 512>>>(x, W_ih, b_ih, b_hh);

    lstm_kernel<<<NBLK, 800>>>(h0, c0, W_hh, W_fc, b_fc, out);
}

// round 8
// speedup vs baseline: 1.0546x; 1.0546x over previous
#include <cuda_runtime.h>
#include <cstdint>

#define B_ 256
#define T_ 1024
#define D_ 64
#define H_ 100
#define G_ 400   // 4*H
#define NBLK 128
#define L2E 1.44269504088896f

// ---------------------------------------------------------------------------
// Packed f32x2 helpers
// ---------------------------------------------------------------------------
__device__ __forceinline__ unsigned long long ffma2(unsigned long long a,
                                                    unsigned long long b,
                                                    unsigned long long c) {
    unsigned long long d;
    asm("fma.rn.f32x2 %0, %1, %2, %3;" : "=l"(d) : "l"(a), "l"(b), "l"(c));
    return d;
}
__device__ __forceinline__ unsigned long long pack2(float x, float y) {
    return ((unsigned long long)__float_as_uint(y) << 32) |
           (unsigned long long)__float_as_uint(x);
}
__device__ __forceinline__ float lo2(unsigned long long v) {
    return __uint_as_float((unsigned)v);
}
__device__ __forceinline__ float hi2(unsigned long long v) {
    return __uint_as_float((unsigned)(v >> 32));
}
__device__ __forceinline__ float ex2a(float x) {
    float r; asm("ex2.approx.ftz.f32 %0, %1;" : "=f"(r) : "f"(x)); return r;
}
__device__ __forceinline__ float rcpa(float x) {
    float r; asm("rcp.approx.ftz.f32 %0, %1;" : "=f"(r) : "f"(x)); return r;
}
// sigmoid(x) = 1 - 1/(e^x+1)  (lm=log2e, s=1);  tanh(x) = 1 - 2/(e^2x+1)
__device__ __forceinline__ float uact(float x, float lm, float s) {
    return 1.0f - s * rcpa(ex2a(lm * x) + 1.0f);
}

// ---------------------------------------------------------------------------
// Shared-memory layout (dynamic, ~105 KB)
// ---------------------------------------------------------------------------
#define SMEM_WSM   0                         // wsm2[16][800] f32x2  = 102400 B
#define SMEM_HS4   (SMEM_WSM + 102400)       // hs4[2][50] float4    = 1600 B
#define SMEM_XB    (SMEM_HS4 + 1600)         // xb4[2][2][16] float4 = 1024 B
#define SMEM_WFC   (SMEM_XB + 1024)          // wfc[100] float       = 400 B
#define SMEM_TOTAL (SMEM_WFC + 512)

// ---------------------------------------------------------------------------
// Fused kernel: LSTM recurrence WITH on-the-fly input-gate GEMM.
// 128 blocks x 2 batch rows, 800 threads. Thread: r = tid>>1 (row: gate=r&3,
// unit j=r>>2), s = tid&1 (k-half + batch owner).
// Per step, accumulators gather BOTH  h(t-1)@W_hh  (k-half of H=100, W in
// regs, h from smem float4)  AND  x(t)@W_ih  (k-half of D=64, W from smem
// thread-owned layout, x from double-buffered smem tile streamed by warp 0).
// 2 shfl.xor combine k-halves; 3 shfl.down gather {f,g,o}; gate-0 lane owns
// c, writes h to the other hs4 buffer. ONE __syncthreads per step.
// xg tensor (419 MB) is never materialized.
// ---------------------------------------------------------------------------
__global__ __launch_bounds__(800, 1)
void lstm_fused_kernel(const float* __restrict__ x,
                       const float* __restrict__ h0,
                       const float* __restrict__ c0,
                       const float* __restrict__ W_ih,
                       const float* __restrict__ W_hh,
                       const float* __restrict__ b_ih,
                       const float* __restrict__ b_hh,
                       const float* __restrict__ W_fc,
                       const float* __restrict__ b_fc,
                       float* __restrict__ out) {
    extern __shared__ char smem[];
    unsigned long long* wsm2 = (unsigned long long*)(smem + SMEM_WSM); // [m*800+tid]
    float4* hs4  = (float4*)(smem + SMEM_HS4);   // [buf*50 + i]
    float4* xb4  = (float4*)(smem + SMEM_XB);    // [buf*32 + b*16 + q]
    float*  wfcs = (float*)(smem + SMEM_WFC);

    const int tid    = threadIdx.x;
    const int batch0 = blockIdx.x * 2;
    const int r      = tid >> 1;       // permuted gate-row index
    const int s      = tid & 1;        // k-half + batch owner
    const int gate   = r & 3;
    const int j      = r >> 2;
    const int row    = gate * H_ + j;  // actual W row

    // --- init h buffer 0, wfc ---
    if (tid < H_) {
        int i = tid >> 1, comp = tid & 1;
        ((float*)&hs4[i])[comp]     = h0[(size_t)(batch0)     * H_ + tid];
        ((float*)&hs4[i])[2 + comp] = h0[(size_t)(batch0 + 1) * H_ + tid];
        wfcs[tid] = W_fc[tid];
    }

    // --- W_hh half-row in registers: k-pairs [s*25, s*25+25) ---
    unsigned long long w2[25];
    {
        const float2* wr = (const float2*)(W_hh + (size_t)row * H_) + s * 25;
#pragma unroll
        for (int i = 0; i < 25; i++) {
            float2 v = wr[i];
            w2[i] = pack2(v.x, v.y);
        }
    }

    // --- W_ih half-row into shared, thread-owned slots: k-pairs [16s,16s+16) ---
    {
        const float2* wi = (const float2*)(W_ih + (size_t)row * D_) + s * 16;
#pragma unroll
        for (int m = 0; m < 16; m++)
            wsm2[m * 800 + tid] = pack2(wi[m].x, wi[m].y);
    }

    const float bias = b_ih[row] + b_hh[row];
    const float lm = (gate == 2) ? 2.0f * L2E : L2E;
    const float sc = (gate == 2) ? 2.0f : 1.0f;

    // c owned by gate-0 threads: (unit j, batch s)
    float cr = (gate == 0) ? c0[(size_t)(batch0 + s) * H_ + j] : 0.0f;

    // --- x stream: warp 0 loads step-0 tile into buffer 0 ---
    const int xb_b = tid >> 4, xb_q = tid & 15;   // loader role (tid<32)
    if (tid < 32) {
        float4 v = *(const float4*)(x + ((size_t)(batch0 + xb_b) * T_) * D_ +
                                    xb_q * 4);
        xb4[xb_b * 16 + xb_q] = v;
    }
    __syncthreads();

    int cur = 0;
    for (int t = 0; t < T_; t++) {
        // prefetch next step's x tile (LDG early, STS late)
        float4 xpre;
        if (tid < 32 && t + 1 < T_) {
            xpre = *(const float4*)(x +
                    ((size_t)(batch0 + xb_b) * T_ + (t + 1)) * D_ + xb_q * 4);
        }

        unsigned long long a0 = 0ull, b0 = 0ull;   // batch0 / batch1 partials

        // ---- h(t-1) @ W_hh over my k-half (25 pairs) ----
        const float4* hbase = hs4 + cur * 50 + s * 25;
#pragma unroll
        for (int i = 0; i < 25; i++) {
            float4 hv = hbase[i];                  // LDS.128 broadcast
            a0 = ffma2(w2[i], pack2(hv.x, hv.y), a0);
            b0 = ffma2(w2[i], pack2(hv.z, hv.w), b0);
        }

        // ---- x(t) @ W_ih over my k-half (16 pairs) ----
        const float4* xc0 = xb4 + cur * 32 + s * 8;        // batch0 quads
        const float4* xc1 = xb4 + cur * 32 + 16 + s * 8;   // batch1 quads
#pragma unroll
        for (int mm = 0; mm < 8; mm++) {
            unsigned long long wa = wsm2[(2 * mm)     * 800 + tid]; // LDS.64
            unsigned long long wb = wsm2[(2 * mm + 1) * 800 + tid];
            float4 xv = xc0[mm];                   // LDS.128 broadcast
            float4 xw = xc1[mm];
            a0 = ffma2(wa, pack2(xv.x, xv.y), a0);
            a0 = ffma2(wb, pack2(xv.z, xv.w), a0);
            b0 = ffma2(wa, pack2(xw.x, xw.y), b0);
            b0 = ffma2(wb, pack2(xw.z, xw.w), b0);
        }

        float p0 = lo2(a0) + hi2(a0);
        float p1 = lo2(b0) + hi2(b0);

        // combine k-halves with partner lane (tid^1)
        float q0 = __shfl_xor_sync(0xffffffffu, p0, 1);
        float q1 = __shfl_xor_sync(0xffffffffu, p1, 1);
        float full = (s ? (p1 + q1) : (p0 + q0)) + bias;

        float gv = uact(full, lm, sc);             // my gate, my batch

        // gather {f,g,o} to gate-0 lane (even deltas keep batch parity)
        float fv = __shfl_down_sync(0xffffffffu, gv, 2);
        float gg = __shfl_down_sync(0xffffffffu, gv, 4);
        float ov = __shfl_down_sync(0xffffffffu, gv, 6);

        if (gate == 0) {                           // owns c for (j, batch s)
            cr = fv * cr + gv * gg;
            float hv = ov * uact(cr, 2.0f * L2E, 2.0f);
            ((float*)&hs4[(cur ^ 1) * 50 + (j >> 1)])[(j & 1) + 2 * s] = hv;
        }

        // publish next x tile into the other buffer
        if (tid < 32 && t + 1 < T_)
            xb4[(cur ^ 1) * 32 + xb_b * 16 + xb_q] = xpre;

        __syncthreads();
        cur ^= 1;
    }

    // FC head: out[b] = h_T . W_fc + b_fc   (h_T in hs4[cur])
    if (tid < 2) {
        float acc = b_fc[0];
#pragma unroll 4
        for (int jj = 0; jj < H_; jj++) {
            float hv = ((const float*)&hs4[cur * 50 + (jj >> 1)])[(jj & 1) + 2 * tid];
            acc += hv * wfcs[jj];
        }
        out[batch0 + tid] = acc;
    }
}

// ---------------------------------------------------------------------------
extern "C" void kernel_launch(void* const* d_in, const int* in_sizes, int n_in,
                              void* d_out, int out_size) {
    const float* x    = (const float*)d_in[0];
    const float* h0   = (const float*)d_in[1];
    const float* c0   = (const float*)d_in[2];
    const float* W_ih = (const float*)d_in[3];
    const float* W_hh = (const float*)d_in[4];
    const float* b_ih = (const float*)d_in[5];
    const float* b_hh = (const float*)d_in[6];
    const float* W_fc = (const float*)d_in[7];
    const float* b_fc = (const float*)d_in[8];
    float* out = (float*)d_out;

    cudaFuncSetAttribute(lstm_fused_kernel,
                         cudaFuncAttributeMaxDynamicSharedMemorySize,
                         SMEM_TOTAL);
    lstm_fused_kernel<<<NBLK, 800, SMEM_TOTAL>>>(
        x, h0, c0, W_ih, W_hh, b_ih, b_hh, W_fc, b_fc, out);
}